// round 3
// baseline (speedup 1.0000x reference)
#include <cuda_runtime.h>

#define PAIRS 80
#define SEQ   2048
#define VD    768
#define HID   512
#define HID2  1024
#define NOUT  5
#define NCHUNK 32
#define ROWS_PER_CHUNK (SEQ / NCHUNK)   // 64

// ---------------- scratch (static device globals; no allocs) ----------------
__device__ float g_X[PAIRS * HID2];     // concat: [:,0:512]=pooled_v, [:,512:1024]=q
__device__ float g_QQ[PAIRS * HID2];
__device__ float g_WKQ[PAIRS * HID];
__device__ float g_U[PAIRS * VD];
__device__ float g_R[PAIRS * VD];
__device__ float g_PH[PAIRS * HID];
__device__ float g_H[PAIRS * HID];
__device__ float g_Pacc[PAIRS * NCHUNK * VD];
__device__ float g_Pm[PAIRS * NCHUNK];
__device__ float g_Pl[PAIRS * NCHUNK];

// ---------------- init: bias-initialize split-K atomic outputs ----------------
__global__ void init_kernel(const float* __restrict__ bqp,
                            const float* __restrict__ bvp,
                            const float* __restrict__ b1) {
    int t = blockIdx.x * blockDim.x + threadIdx.x;
    if (t < PAIRS * HID2) {
        int col = t & (HID2 - 1);
        g_X[t]  = (col < HID) ? 0.f : bqp[col - HID];
        g_QQ[t] = 0.f;
    }
    if (t < PAIRS * HID) {
        int col = t & (HID - 1);
        g_WKQ[t] = 0.f;
        g_PH[t]  = bvp[col];
        g_H[t]   = b1[col];
    }
    if (t < PAIRS * VD) g_U[t] = 0.f;
}

// ---------------- skinny GEMM, deep register blocking ------------------------
// out[p][r] += scale * sum_k in[p][k] * W(k,r)
// Tile: 16 pairs x (2*RHALF) r, k-slab 16 per block (split-K via blockIdx.z).
// Thread micro-tile: 8 pairs x 8 r (two f4 column groups at 4tr and RHALF+4tr)
// => 64 acc, 16 LDS-floats per 64 FFMA = 1 B/FLOP (SM smem port no longer binding).
// TN: W is [K, R] (reduce over rows). NT: W is [R, K] row-major.
template <bool TN, int RHALF>
__global__ __launch_bounds__(RHALF / 2)
void gemm_sk(const float* __restrict__ in, int in_ld,
             const float* __restrict__ W, int wld,
             float* __restrict__ out, int out_ld,
             float scale) {
    constexpr int THREADS = RHALF / 2;
    constexpr int RT = 2 * RHALF;

    __shared__ float As[16][16];   // [kk][pair]
    __shared__ float Bs[16][RT];   // [kk][r]

    const int tx = threadIdx.x;
    const int p0 = blockIdx.y * 16;
    const int r0 = blockIdx.x * RT;
    const int k0 = blockIdx.z * 16;

    // As: 16 pairs x 16 k, stored transposed [kk][p]
    for (int f = tx; f < 256; f += THREADS) {
        int kk = f >> 4, p = f & 15;
        As[kk][p] = in[(size_t)(p0 + p) * in_ld + k0 + kk];
    }
    // Bs: 16 k x RT r
    if (TN) {
        constexpr int F4R = RT / 4;
        for (int f = tx; f < 16 * F4R; f += THREADS) {
            int kk = f / F4R, c = f % F4R;
            *(float4*)&Bs[kk][4 * c] =
                *(const float4*)(W + (size_t)(k0 + kk) * wld + r0 + 4 * c);
        }
    } else {
        for (int f = tx; f < RT * 4; f += THREADS) {
            int r = f >> 2, q = f & 3;
            float4 v = *(const float4*)(W + (size_t)(r0 + r) * wld + k0 + 4 * q);
            Bs[4 * q + 0][r] = v.x;
            Bs[4 * q + 1][r] = v.y;
            Bs[4 * q + 2][r] = v.z;
            Bs[4 * q + 3][r] = v.w;
        }
    }
    __syncthreads();

    const int tp = tx / (RHALF / 4);   // 0..1 -> 8-pair group
    const int tr = tx % (RHALF / 4);   // f4 column within half

    float acc0[8][4], acc1[8][4];
#pragma unroll
    for (int i = 0; i < 8; i++)
#pragma unroll
        for (int j = 0; j < 4; j++) { acc0[i][j] = 0.f; acc1[i][j] = 0.f; }

#pragma unroll
    for (int kk = 0; kk < 16; kk++) {
        float4 av0 = *(const float4*)&As[kk][tp * 8];       // broadcast
        float4 av1 = *(const float4*)&As[kk][tp * 8 + 4];   // broadcast
        float4 b0  = *(const float4*)&Bs[kk][4 * tr];
        float4 b1  = *(const float4*)&Bs[kk][RHALF + 4 * tr];
        float a[8] = {av0.x, av0.y, av0.z, av0.w, av1.x, av1.y, av1.z, av1.w};
        float c0[4] = {b0.x, b0.y, b0.z, b0.w};
        float c1[4] = {b1.x, b1.y, b1.z, b1.w};
#pragma unroll
        for (int i = 0; i < 8; i++) {
#pragma unroll
            for (int j = 0; j < 4; j++) {
                acc0[i][j] += a[i] * c0[j];
                acc1[i][j] += a[i] * c1[j];
            }
        }
    }

#pragma unroll
    for (int i = 0; i < 8; i++) {
        float* o = out + (size_t)(p0 + tp * 8 + i) * out_ld + r0;
#pragma unroll
        for (int j = 0; j < 4; j++) {
            atomicAdd(o + 4 * tr + j,          acc0[i][j] * scale);
            atomicAdd(o + RHALF + 4 * tr + j,  acc1[i][j] * scale);
        }
    }
}

// ---------------- flash: scores + online-softmax pooled accumulation ----------------
// grid = (NCHUNK, PAIRS), 256 threads (8 warps). Warp handles rows w, w+8, ...
// u in smem; rescale only when running max rises (warp-uniform branch).
__global__ __launch_bounds__(256)
void flash_kernel(const float* __restrict__ video) {
    const int chunk = blockIdx.x;
    const int pair  = blockIdx.y;
    const int t = threadIdx.x;
    const int w = t >> 5, lane = t & 31;

    __shared__ float su[VD];
    __shared__ float sm[8], sl[8];
    __shared__ float sacc[8][VD];

    for (int d = t; d < VD; d += 256) su[d] = g_U[(size_t)pair * VD + d];
    __syncthreads();
    const float4* su4 = (const float4*)su;

    float m = -1e30f, l = 0.f;
    float4 acc[6];
#pragma unroll
    for (int j = 0; j < 6; j++) acc[j] = make_float4(0.f, 0.f, 0.f, 0.f);

    const float* base = video + ((size_t)pair * SEQ + (size_t)chunk * ROWS_PER_CHUNK) * VD;

    for (int r = w; r < ROWS_PER_CHUNK; r += 8) {
        const float4* x4 = (const float4*)(base + (size_t)r * VD);
        float4 xv[6];
#pragma unroll
        for (int j = 0; j < 6; j++) xv[j] = x4[lane + 32 * j];
        float s = 0.f;
#pragma unroll
        for (int j = 0; j < 6; j++) {
            float4 uv = su4[lane + 32 * j];
            s += xv[j].x * uv.x + xv[j].y * uv.y + xv[j].z * uv.z + xv[j].w * uv.w;
        }
#pragma unroll
        for (int o = 16; o > 0; o >>= 1) s += __shfl_xor_sync(0xffffffffu, s, o);

        if (s > m) {
            float corr = __expf(m - s);
            l *= corr;
#pragma unroll
            for (int j = 0; j < 6; j++) {
                acc[j].x *= corr; acc[j].y *= corr;
                acc[j].z *= corr; acc[j].w *= corr;
            }
            m = s;
        }
        float p = __expf(s - m);
        l += p;
#pragma unroll
        for (int j = 0; j < 6; j++) {
            acc[j].x += p * xv[j].x; acc[j].y += p * xv[j].y;
            acc[j].z += p * xv[j].z; acc[j].w += p * xv[j].w;
        }
    }

    if (lane == 0) { sm[w] = m; sl[w] = l; }
    float4* sa4 = (float4*)sacc[w];
#pragma unroll
    for (int j = 0; j < 6; j++) sa4[lane + 32 * j] = acc[j];
    __syncthreads();

    float M = sm[0];
#pragma unroll
    for (int i = 1; i < 8; i++) M = fmaxf(M, sm[i]);
    float wsc[8], L = 0.f;
#pragma unroll
    for (int i = 0; i < 8; i++) { wsc[i] = __expf(sm[i] - M); L += wsc[i] * sl[i]; }

    for (int d = t; d < VD; d += 256) {
        float a = 0.f;
#pragma unroll
        for (int i = 0; i < 8; i++) a += wsc[i] * sacc[i][d];
        g_Pacc[((size_t)pair * NCHUNK + chunk) * VD + d] = a;
    }
    if (t == 0) { g_Pm[pair * NCHUNK + chunk] = M; g_Pl[pair * NCHUNK + chunk] = L; }
}

// ---------------- combine split-S partials -> r = attn^T @ video ----------------
__global__ __launch_bounds__(256)
void combine_kernel() {
    const int pair = blockIdx.x, t = threadIdx.x;
    __shared__ float wsc[NCHUNK];
    __shared__ float sInvL;
    if (t == 0) {
        float M = g_Pm[pair * NCHUNK];
        for (int c = 1; c < NCHUNK; c++) M = fmaxf(M, g_Pm[pair * NCHUNK + c]);
        float L = 0.f;
        for (int c = 0; c < NCHUNK; c++) {
            float e = __expf(g_Pm[pair * NCHUNK + c] - M);
            wsc[c] = e;
            L += e * g_Pl[pair * NCHUNK + c];
        }
        sInvL = 1.f / L;
    }
    __syncthreads();
    const float invL = sInvL;
    for (int d = t; d < VD; d += 256) {
        float a = 0.f;
#pragma unroll
        for (int c = 0; c < NCHUNK; c++)
            a += wsc[c] * g_Pacc[((size_t)pair * NCHUNK + c) * VD + d];
        g_R[(size_t)pair * VD + d] = a * invL;
    }
}

// ---------------- final: out = softmax(relu(h) @ W2^T + b2 + mask) ----------------
__global__ __launch_bounds__(32)
void final_kernel(const float* __restrict__ W2, const float* __restrict__ b2,
                  const float* __restrict__ omask, float* __restrict__ out) {
    const int pair = blockIdx.x, lane = threadIdx.x;
    float o[NOUT] = {0.f, 0.f, 0.f, 0.f, 0.f};
    for (int h = lane; h < HID; h += 32) {
        float hv = fmaxf(g_H[pair * HID + h], 0.f);
#pragma unroll
        for (int j = 0; j < NOUT; j++) o[j] += hv * W2[j * HID + h];
    }
#pragma unroll
    for (int j = 0; j < NOUT; j++)
#pragma unroll
        for (int off = 16; off > 0; off >>= 1)
            o[j] += __shfl_xor_sync(0xffffffffu, o[j], off);
    if (lane == 0) {
        float x[NOUT], mx = -1e30f;
#pragma unroll
        for (int j = 0; j < NOUT; j++) {
            x[j] = o[j] + b2[j] + omask[pair * NOUT + j];
            mx = fmaxf(mx, x[j]);
        }
        float e[NOUT], s = 0.f;
#pragma unroll
        for (int j = 0; j < NOUT; j++) { e[j] = __expf(x[j] - mx); s += e[j]; }
#pragma unroll
        for (int j = 0; j < NOUT; j++) out[pair * NOUT + j] = e[j] / s;
    }
}

// ---------------- launch ----------------
extern "C" void kernel_launch(void* const* d_in, const int* in_sizes, int n_in,
                              void* d_out, int out_size) {
    (void)in_sizes; (void)n_in; (void)out_size;
    const float* video = (const float*)d_in[0];
    const float* ques  = (const float*)d_in[1];
    const float* omask = (const float*)d_in[3];
    const float* Wvp   = (const float*)d_in[4];
    const float* bvp   = (const float*)d_in[5];
    const float* Wqp   = (const float*)d_in[6];
    const float* bqp   = (const float*)d_in[7];
    const float* Wk    = (const float*)d_in[8];
    const float* Wv    = (const float*)d_in[9];
    const float* Wq    = (const float*)d_in[10];
    const float* W1    = (const float*)d_in[11];
    const float* b1    = (const float*)d_in[12];
    const float* W2    = (const float*)d_in[13];
    const float* b2    = (const float*)d_in[14];
    float* out = (float*)d_out;

    float *X, *QQ, *WKQ, *U, *R, *PH, *H;
    cudaGetSymbolAddress((void**)&X,   g_X);
    cudaGetSymbolAddress((void**)&QQ,  g_QQ);
    cudaGetSymbolAddress((void**)&WKQ, g_WKQ);
    cudaGetSymbolAddress((void**)&U,   g_U);
    cudaGetSymbolAddress((void**)&R,   g_R);
    cudaGetSymbolAddress((void**)&PH,  g_PH);
    cudaGetSymbolAddress((void**)&H,   g_H);

    // biases into atomic-accumulated outputs
    init_kernel<<<(PAIRS * HID2 + 255) / 256, 256>>>(bqp, bvp, b1);
    // q = ques[:,:,0,:] @ Wqp^T + bqp  -> X[:,512:]   (K=768, R=512)
    gemm_sk<false, 256><<<dim3(1, 5, 48), 128>>>(ques, 32 * VD, Wqp, VD, X + HID, HID2, 1.f);
    // qq = q @ Wq^T                                    (K=512, R=1024)
    gemm_sk<false, 256><<<dim3(2, 5, 32), 128>>>(X + HID, HID2, Wq, HID, QQ, HID2, 1.f);
    // wkq = Wk^T @ qq                                  (K=1024, R=512)
    gemm_sk<true, 256><<<dim3(1, 5, 64), 128>>>(QQ, HID2, Wk, HID, WKQ, HID, 1.f);
    // u = Wvp^T @ wkq / sqrt(2H)                       (K=512, R=768)
    gemm_sk<true, 384><<<dim3(1, 5, 32), 192>>>(WKQ, HID, Wvp, VD, U, VD, 1.f / 32.f);
    // flash: single HBM pass over video_enc
    flash_kernel<<<dim3(NCHUNK, PAIRS), 256>>>(video);
    combine_kernel<<<PAIRS, 256>>>();
    // pooled_h = r @ Wvp^T + bvp                        (K=768, R=512)
    gemm_sk<false, 256><<<dim3(1, 5, 48), 128>>>(R, VD, Wvp, VD, PH, HID, 1.f);
    // pooled_v = pooled_h @ Wv^T -> X[:, :512]          (K=512, R=512)
    gemm_sk<false, 256><<<dim3(1, 5, 32), 128>>>(PH, HID, Wv, HID, X, HID2, 1.f);
    // h = X @ W1^T + b1 (relu deferred)                 (K=1024, R=512)
    gemm_sk<false, 256><<<dim3(1, 5, 64), 128>>>(X, HID2, W1, HID2, H, HID, 1.f);
    // out = softmax(relu(h) @ W2^T + b2 + output_mask)
    final_kernel<<<PAIRS, 32>>>(W2, b2, omask, out);
}

// round 4
// speedup vs baseline: 1.2454x; 1.2454x over previous
#include <cuda_runtime.h>

#define PAIRS 80
#define SEQ   2048
#define VD    768
#define HID   512
#define HID2  1024
#define NOUT  5
#define NCHUNK 32
#define ROWS_PER_CHUNK (SEQ / NCHUNK)   // 64

// ---------------- scratch (static device globals; no allocs) ----------------
__device__ float g_X[PAIRS * HID2];     // concat: [:,0:512]=pooled_v, [:,512:1024]=q
__device__ float g_QQ[PAIRS * HID2];
__device__ float g_WKQ[PAIRS * HID];
__device__ float g_U[PAIRS * VD];
__device__ float g_R[PAIRS * VD];
__device__ float g_PH[PAIRS * HID];
__device__ float g_H[PAIRS * HID];
__device__ float g_Pacc[PAIRS * NCHUNK * VD];
__device__ float g_Pm[PAIRS * NCHUNK];
__device__ float g_Pl[PAIRS * NCHUNK];

// ---------------- init: bias-initialize split-K atomic outputs ----------------
__global__ void init_kernel(const float* __restrict__ bqp,
                            const float* __restrict__ bvp,
                            const float* __restrict__ b1) {
    int t = blockIdx.x * blockDim.x + threadIdx.x;
    if (t < PAIRS * HID2) {
        int col = t & (HID2 - 1);
        g_X[t]  = (col < HID) ? 0.f : bqp[col - HID];
        g_QQ[t] = 0.f;
    }
    if (t < PAIRS * HID) {
        int col = t & (HID - 1);
        g_WKQ[t] = 0.f;
        g_PH[t]  = bvp[col];
        g_H[t]   = b1[col];
    }
    if (t < PAIRS * VD) g_U[t] = 0.f;
}

// ---------------- skinny GEMM, double-buffered smem pipeline -----------------
// out[p][r] += scale * sum_k in[p][k] * W(k,r)
// Tile: 16 pairs x 64 r, k-step 64, kchunk per block (split-K via blockIdx.z).
// 256 threads, acc[4]/thread. Global loads for tile it+1 are issued before the
// compute of tile it (register prefetch -> alternate smem buffer, 1 sync/iter).
// TN: W is [K, R]. NT: W is [R, K] row-major.
template <bool TN>
__global__ __launch_bounds__(256)
void gemm_db(const float* __restrict__ in, int in_ld,
             const float* __restrict__ W, int wld,
             float* __restrict__ out, int out_ld,
             int kchunk, float scale) {
    __shared__ float As[2][16][68];
    __shared__ float Bs[2][64][68];

    const int tx = threadIdx.x;
    const int ty = tx >> 4;        // 0..15 : pair index / k-row group
    const int tc = tx & 15;        // 0..15 : f4 column group
    const int r0 = blockIdx.x * 64;
    const int p0 = blockIdx.y * 16;
    const int kbase = blockIdx.z * kchunk;
    const int niter = kchunk >> 6;

    const float* inp = in + (size_t)(p0 + ty) * in_ld + 4 * tc;

    float4 a_pf;
    float4 b_pf[4];

    // ---- prefetch tile 0 ----
    {
        const int k0 = kbase;
        a_pf = *(const float4*)(inp + k0);
        if (TN) {
#pragma unroll
            for (int i = 0; i < 4; i++)
                b_pf[i] = *(const float4*)(W + (size_t)(k0 + ty + 16 * i) * wld + r0 + 4 * tc);
        } else {
#pragma unroll
            for (int i = 0; i < 4; i++)
                b_pf[i] = *(const float4*)(W + (size_t)(r0 + tc + 16 * i) * wld + k0 + 4 * ty);
        }
    }
    // ---- store tile 0 into buf 0 ----
    *(float4*)&As[0][ty][4 * tc] = a_pf;
    if (TN) {
#pragma unroll
        for (int i = 0; i < 4; i++)
            *(float4*)&Bs[0][ty + 16 * i][4 * tc] = b_pf[i];
    } else {
#pragma unroll
        for (int i = 0; i < 4; i++) {
            Bs[0][4 * ty + 0][tc + 16 * i] = b_pf[i].x;
            Bs[0][4 * ty + 1][tc + 16 * i] = b_pf[i].y;
            Bs[0][4 * ty + 2][tc + 16 * i] = b_pf[i].z;
            Bs[0][4 * ty + 3][tc + 16 * i] = b_pf[i].w;
        }
    }
    __syncthreads();

    float acc[4] = {0.f, 0.f, 0.f, 0.f};

    for (int it = 0; it < niter; it++) {
        const int cur = it & 1;
        const bool more = (it + 1 < niter);
        // issue global loads for next tile (overlaps with compute below)
        if (more) {
            const int k0 = kbase + (it + 1) * 64;
            a_pf = *(const float4*)(inp + k0);
            if (TN) {
#pragma unroll
                for (int i = 0; i < 4; i++)
                    b_pf[i] = *(const float4*)(W + (size_t)(k0 + ty + 16 * i) * wld + r0 + 4 * tc);
            } else {
#pragma unroll
                for (int i = 0; i < 4; i++)
                    b_pf[i] = *(const float4*)(W + (size_t)(r0 + tc + 16 * i) * wld + k0 + 4 * ty);
            }
        }
        // compute current tile
#pragma unroll
        for (int kk = 0; kk < 64; kk++) {
            float a = As[cur][ty][kk];
            float4 b = *(const float4*)&Bs[cur][kk][4 * tc];
            acc[0] += a * b.x; acc[1] += a * b.y;
            acc[2] += a * b.z; acc[3] += a * b.w;
        }
        // store prefetched tile into alternate buffer
        if (more) {
            const int nxt = cur ^ 1;
            *(float4*)&As[nxt][ty][4 * tc] = a_pf;
            if (TN) {
#pragma unroll
                for (int i = 0; i < 4; i++)
                    *(float4*)&Bs[nxt][ty + 16 * i][4 * tc] = b_pf[i];
            } else {
#pragma unroll
                for (int i = 0; i < 4; i++) {
                    Bs[nxt][4 * ty + 0][tc + 16 * i] = b_pf[i].x;
                    Bs[nxt][4 * ty + 1][tc + 16 * i] = b_pf[i].y;
                    Bs[nxt][4 * ty + 2][tc + 16 * i] = b_pf[i].z;
                    Bs[nxt][4 * ty + 3][tc + 16 * i] = b_pf[i].w;
                }
            }
        }
        __syncthreads();
    }

#pragma unroll
    for (int j = 0; j < 4; j++)
        atomicAdd(&out[(size_t)(p0 + ty) * out_ld + r0 + 4 * tc + j], acc[j] * scale);
}

// ---------------- flash: scores + online-softmax pooled accumulation ----------------
// grid = (NCHUNK, PAIRS), 256 threads (8 warps). Warp handles rows w, w+8, ...
// u in smem; rescale only when running max rises (warp-uniform branch).
__global__ __launch_bounds__(256)
void flash_kernel(const float* __restrict__ video) {
    const int chunk = blockIdx.x;
    const int pair  = blockIdx.y;
    const int t = threadIdx.x;
    const int w = t >> 5, lane = t & 31;

    __shared__ float su[VD];
    __shared__ float sm[8], sl[8];
    __shared__ float sacc[8][VD];

    for (int d = t; d < VD; d += 256) su[d] = g_U[(size_t)pair * VD + d];
    __syncthreads();
    const float4* su4 = (const float4*)su;

    float m = -1e30f, l = 0.f;
    float4 acc[6];
#pragma unroll
    for (int j = 0; j < 6; j++) acc[j] = make_float4(0.f, 0.f, 0.f, 0.f);

    const float* base = video + ((size_t)pair * SEQ + (size_t)chunk * ROWS_PER_CHUNK) * VD;

    for (int r = w; r < ROWS_PER_CHUNK; r += 8) {
        const float4* x4 = (const float4*)(base + (size_t)r * VD);
        float4 xv[6];
#pragma unroll
        for (int j = 0; j < 6; j++) xv[j] = x4[lane + 32 * j];
        float s = 0.f;
#pragma unroll
        for (int j = 0; j < 6; j++) {
            float4 uv = su4[lane + 32 * j];
            s += xv[j].x * uv.x + xv[j].y * uv.y + xv[j].z * uv.z + xv[j].w * uv.w;
        }
#pragma unroll
        for (int o = 16; o > 0; o >>= 1) s += __shfl_xor_sync(0xffffffffu, s, o);

        if (s > m) {
            float corr = __expf(m - s);
            l *= corr;
#pragma unroll
            for (int j = 0; j < 6; j++) {
                acc[j].x *= corr; acc[j].y *= corr;
                acc[j].z *= corr; acc[j].w *= corr;
            }
            m = s;
        }
        float p = __expf(s - m);
        l += p;
#pragma unroll
        for (int j = 0; j < 6; j++) {
            acc[j].x += p * xv[j].x; acc[j].y += p * xv[j].y;
            acc[j].z += p * xv[j].z; acc[j].w += p * xv[j].w;
        }
    }

    if (lane == 0) { sm[w] = m; sl[w] = l; }
    float4* sa4 = (float4*)sacc[w];
#pragma unroll
    for (int j = 0; j < 6; j++) sa4[lane + 32 * j] = acc[j];
    __syncthreads();

    float M = sm[0];
#pragma unroll
    for (int i = 1; i < 8; i++) M = fmaxf(M, sm[i]);
    float wsc[8], L = 0.f;
#pragma unroll
    for (int i = 0; i < 8; i++) { wsc[i] = __expf(sm[i] - M); L += wsc[i] * sl[i]; }

    for (int d = t; d < VD; d += 256) {
        float a = 0.f;
#pragma unroll
        for (int i = 0; i < 8; i++) a += wsc[i] * sacc[i][d];
        g_Pacc[((size_t)pair * NCHUNK + chunk) * VD + d] = a;
    }
    if (t == 0) { g_Pm[pair * NCHUNK + chunk] = M; g_Pl[pair * NCHUNK + chunk] = L; }
}

// ---------------- combine split-S partials -> r = attn^T @ video ----------------
__global__ __launch_bounds__(256)
void combine_kernel() {
    const int pair = blockIdx.x, t = threadIdx.x;
    __shared__ float wsc[NCHUNK];
    __shared__ float sInvL;
    if (t == 0) {
        float M = g_Pm[pair * NCHUNK];
        for (int c = 1; c < NCHUNK; c++) M = fmaxf(M, g_Pm[pair * NCHUNK + c]);
        float L = 0.f;
        for (int c = 0; c < NCHUNK; c++) {
            float e = __expf(g_Pm[pair * NCHUNK + c] - M);
            wsc[c] = e;
            L += e * g_Pl[pair * NCHUNK + c];
        }
        sInvL = 1.f / L;
    }
    __syncthreads();
    const float invL = sInvL;
    for (int d = t; d < VD; d += 256) {
        float a = 0.f;
#pragma unroll
        for (int c = 0; c < NCHUNK; c++)
            a += wsc[c] * g_Pacc[((size_t)pair * NCHUNK + c) * VD + d];
        g_R[(size_t)pair * VD + d] = a * invL;
    }
}

// ---------------- final: out = softmax(relu(h) @ W2^T + b2 + mask) ----------------
__global__ __launch_bounds__(32)
void final_kernel(const float* __restrict__ W2, const float* __restrict__ b2,
                  const float* __restrict__ omask, float* __restrict__ out) {
    const int pair = blockIdx.x, lane = threadIdx.x;
    float o[NOUT] = {0.f, 0.f, 0.f, 0.f, 0.f};
    for (int h = lane; h < HID; h += 32) {
        float hv = fmaxf(g_H[pair * HID + h], 0.f);
#pragma unroll
        for (int j = 0; j < NOUT; j++) o[j] += hv * W2[j * HID + h];
    }
#pragma unroll
    for (int j = 0; j < NOUT; j++)
#pragma unroll
        for (int off = 16; off > 0; off >>= 1)
            o[j] += __shfl_xor_sync(0xffffffffu, o[j], off);
    if (lane == 0) {
        float x[NOUT], mx = -1e30f;
#pragma unroll
        for (int j = 0; j < NOUT; j++) {
            x[j] = o[j] + b2[j] + omask[pair * NOUT + j];
            mx = fmaxf(mx, x[j]);
        }
        float e[NOUT], s = 0.f;
#pragma unroll
        for (int j = 0; j < NOUT; j++) { e[j] = __expf(x[j] - mx); s += e[j]; }
#pragma unroll
        for (int j = 0; j < NOUT; j++) out[pair * NOUT + j] = e[j] / s;
    }
}

// ---------------- launch ----------------
extern "C" void kernel_launch(void* const* d_in, const int* in_sizes, int n_in,
                              void* d_out, int out_size) {
    (void)in_sizes; (void)n_in; (void)out_size;
    const float* video = (const float*)d_in[0];
    const float* ques  = (const float*)d_in[1];
    const float* omask = (const float*)d_in[3];
    const float* Wvp   = (const float*)d_in[4];
    const float* bvp   = (const float*)d_in[5];
    const float* Wqp   = (const float*)d_in[6];
    const float* bqp   = (const float*)d_in[7];
    const float* Wk    = (const float*)d_in[8];
    const float* Wv    = (const float*)d_in[9];
    const float* Wq    = (const float*)d_in[10];
    const float* W1    = (const float*)d_in[11];
    const float* b1    = (const float*)d_in[12];
    const float* W2    = (const float*)d_in[13];
    const float* b2    = (const float*)d_in[14];
    float* out = (float*)d_out;

    float *X, *QQ, *WKQ, *U, *R, *PH, *H;
    cudaGetSymbolAddress((void**)&X,   g_X);
    cudaGetSymbolAddress((void**)&QQ,  g_QQ);
    cudaGetSymbolAddress((void**)&WKQ, g_WKQ);
    cudaGetSymbolAddress((void**)&U,   g_U);
    cudaGetSymbolAddress((void**)&R,   g_R);
    cudaGetSymbolAddress((void**)&PH,  g_PH);
    cudaGetSymbolAddress((void**)&H,   g_H);

    dim3 blk(256);

    // biases into atomic-accumulated outputs
    init_kernel<<<(PAIRS * HID2 + 255) / 256, 256>>>(bqp, bvp, b1);
    // q = ques[:,:,0,:] @ Wqp^T + bqp -> X[:,512:]   (K=768, R=512)
    gemm_db<false><<<dim3(8, 5, 3), blk>>>(ques, 32 * VD, Wqp, VD, X + HID, HID2, 256, 1.f);
    // qq = q @ Wq^T                                   (K=512, R=1024)
    gemm_db<false><<<dim3(16, 5, 2), blk>>>(X + HID, HID2, Wq, HID, QQ, HID2, 256, 1.f);
    // wkq = Wk^T @ qq                                 (K=1024, R=512)
    gemm_db<true ><<<dim3(8, 5, 4), blk>>>(QQ, HID2, Wk, HID, WKQ, HID, 256, 1.f);
    // u = Wvp^T @ wkq / sqrt(2H)                      (K=512, R=768)
    gemm_db<true ><<<dim3(12, 5, 2), blk>>>(WKQ, HID, Wvp, VD, U, VD, 256, 1.f / 32.f);
    // flash: single HBM pass over video_enc
    flash_kernel<<<dim3(NCHUNK, PAIRS), 256>>>(video);
    combine_kernel<<<PAIRS, 256>>>();
    // pooled_h = r @ Wvp^T + bvp                       (K=768, R=512)
    gemm_db<false><<<dim3(8, 5, 3), blk>>>(R, VD, Wvp, VD, PH, HID, 256, 1.f);
    // pooled_v = pooled_h @ Wv^T -> X[:, :512]         (K=512, R=512)
    gemm_db<false><<<dim3(8, 5, 2), blk>>>(PH, HID, Wv, HID, X, HID2, 256, 1.f);
    // h = X @ W1^T + b1 (relu deferred)                (K=1024, R=512)
    gemm_db<false><<<dim3(8, 5, 4), blk>>>(X, HID2, W1, HID2, H, HID, 256, 1.f);
    // out = softmax(relu(h) @ W2^T + b2 + output_mask)
    final_kernel<<<PAIRS, 32>>>(W2, b2, omask, out);
}

// round 5
// speedup vs baseline: 1.2506x; 1.0041x over previous
#include <cuda_runtime.h>

#define PAIRS 80
#define SEQ   2048
#define VD    768
#define HID   512
#define HID2  1024
#define NOUT  5
#define NCHUNK 16
#define ROWS_PER_CHUNK (SEQ / NCHUNK)   // 128

// ---------------- scratch (static device globals; no allocs) ----------------
__device__ float g_X[PAIRS * HID2];     // concat: [:,0:512]=pooled_v, [:,512:1024]=q
__device__ float g_QQ[PAIRS * HID2];
__device__ float g_WKQ[PAIRS * HID];
__device__ float g_U[PAIRS * VD];
__device__ float g_R[PAIRS * VD];
__device__ float g_PH[PAIRS * HID];
__device__ float g_H[PAIRS * HID];
__device__ float g_Pacc[PAIRS * NCHUNK * VD];
__device__ float g_Pm[PAIRS * NCHUNK];
__device__ float g_Pl[PAIRS * NCHUNK];

// ---------------- init: bias-initialize split-K atomic outputs ----------------
__global__ void init_kernel(const float* __restrict__ bqp,
                            const float* __restrict__ bvp,
                            const float* __restrict__ b1) {
    int t = blockIdx.x * blockDim.x + threadIdx.x;
    if (t < PAIRS * HID2) {
        int col = t & (HID2 - 1);
        g_X[t]  = (col < HID) ? 0.f : bqp[col - HID];
        g_QQ[t] = 0.f;
    }
    if (t < PAIRS * HID) {
        int col = t & (HID - 1);
        g_WKQ[t] = 0.f;
        g_PH[t]  = bvp[col];
        g_H[t]   = b1[col];
    }
    if (t < PAIRS * VD) g_U[t] = 0.f;
}

// ---------------- skinny GEMM v2: warp-dedup operand reads --------------------
// out[p][r] += scale * sum_k in[p][k] * W(k,r)
// Block: 128 threads, tile 16 pairs x 128 r, k-step 32, double-buffered.
// Warp w covers r in [32w,32w+32); lane: tp=lane>>3 (pair group), tr=lane&7.
// Thread: 4 pairs x 4 r = 16 acc. Per kk per warp: a = 4 distinct 16B chunks
// (1 LDS wavefront), b = 8 distinct 16B chunks = 128B (1 wavefront) -> 2
// wavefronts per 16 FFMA (was 5 per 4 in R4): FFMA-bound, not crossbar-bound.
// TN: W is [K, R]. NT: W is [R, K] row-major.
template <bool TN>
__global__ __launch_bounds__(128)
void gemm_v2(const float* __restrict__ in, int in_ld,
             const float* __restrict__ W, int wld,
             float* __restrict__ out, int out_ld,
             int kchunk, float scale) {
    __shared__ float As[2][32][20];    // [kk][pair], 20-pad: 16B-aligned rows, conflict-free
    __shared__ float Bs[2][32][132];   // [kk][r],  132-pad: 16B-aligned, store scatter conflict-free

    const int tx = threadIdx.x;
    const int r0 = blockIdx.x * 128;
    const int p0 = blockIdx.y * 16;
    const int kbase = blockIdx.z * kchunk;
    const int niter = kchunk >> 5;

    const int ap  = tx >> 3;   // 0..15 pair for A load
    const int akq = tx & 7;    // f4 k-group for A load

    float4 apf;
    float4 bpf[8];

    // ---- global -> regs for tile starting at k0 ----
    auto ldtile = [&](int k0) {
        apf = *(const float4*)(in + (size_t)(p0 + ap) * in_ld + k0 + 4 * akq);
        if (TN) {
#pragma unroll
            for (int i = 0; i < 8; i++) {
                int idx = tx + 128 * i;
                int kk = idx >> 5, c = idx & 31;
                bpf[i] = *(const float4*)(W + (size_t)(k0 + kk) * wld + r0 + 4 * c);
            }
        } else {
#pragma unroll
            for (int i = 0; i < 8; i++) {
                int idx = tx + 128 * i;
                int r = idx >> 3, kq = idx & 7;
                bpf[i] = *(const float4*)(W + (size_t)(r0 + r) * wld + k0 + 4 * kq);
            }
        }
    };
    // ---- regs -> smem buffer ----
    auto sttile = [&](int buf) {
        As[buf][4 * akq + 0][ap] = apf.x;
        As[buf][4 * akq + 1][ap] = apf.y;
        As[buf][4 * akq + 2][ap] = apf.z;
        As[buf][4 * akq + 3][ap] = apf.w;
        if (TN) {
#pragma unroll
            for (int i = 0; i < 8; i++) {
                int idx = tx + 128 * i;
                int kk = idx >> 5, c = idx & 31;
                *(float4*)&Bs[buf][kk][4 * c] = bpf[i];
            }
        } else {
#pragma unroll
            for (int i = 0; i < 8; i++) {
                int idx = tx + 128 * i;
                int r = idx >> 3, kq = idx & 7;
                Bs[buf][4 * kq + 0][r] = bpf[i].x;
                Bs[buf][4 * kq + 1][r] = bpf[i].y;
                Bs[buf][4 * kq + 2][r] = bpf[i].z;
                Bs[buf][4 * kq + 3][r] = bpf[i].w;
            }
        }
    };

    ldtile(kbase);
    sttile(0);
    __syncthreads();

    const int w = tx >> 5;
    const int lane = tx & 31;
    const int tp = lane >> 3;           // pair group (4 pairs)
    const int rcol = 32 * w + 4 * (lane & 7);

    float acc[4][4];
#pragma unroll
    for (int i = 0; i < 4; i++)
#pragma unroll
        for (int j = 0; j < 4; j++) acc[i][j] = 0.f;

    for (int it = 0; it < niter; it++) {
        const int cur = it & 1;
        const bool more = (it + 1 < niter);
        if (more) ldtile(kbase + 32 * (it + 1));
#pragma unroll
        for (int kk = 0; kk < 32; kk++) {
            float4 a4 = *(const float4*)&As[cur][kk][4 * tp];
            float4 b4 = *(const float4*)&Bs[cur][kk][rcol];
            float a[4] = {a4.x, a4.y, a4.z, a4.w};
            float b[4] = {b4.x, b4.y, b4.z, b4.w};
#pragma unroll
            for (int i = 0; i < 4; i++)
#pragma unroll
                for (int j = 0; j < 4; j++)
                    acc[i][j] += a[i] * b[j];
        }
        if (more) sttile(cur ^ 1);
        __syncthreads();
    }

#pragma unroll
    for (int i = 0; i < 4; i++) {
        float* o = out + (size_t)(p0 + 4 * tp + i) * out_ld + r0 + rcol;
#pragma unroll
        for (int j = 0; j < 4; j++)
            atomicAdd(o + j, acc[i][j] * scale);
    }
}

// ---------------- flash: scores + online-softmax pooled accumulation ----------------
// R1 structure: u in REGISTERS (no smem crossbar traffic for u), NCHUNK=16,
// 256 threads (8 warps), no occupancy cap (avoid spills). Conditional rescale.
__global__ __launch_bounds__(256)
void flash_kernel(const float* __restrict__ video) {
    const int chunk = blockIdx.x;
    const int pair  = blockIdx.y;
    const int t = threadIdx.x;
    const int w = t >> 5, lane = t & 31;

    const float4* u4 = (const float4*)(g_U + (size_t)pair * VD);
    float4 uv[6];
#pragma unroll
    for (int j = 0; j < 6; j++) uv[j] = u4[lane + 32 * j];

    float m = -1e30f, l = 0.f;
    float4 acc[6];
#pragma unroll
    for (int j = 0; j < 6; j++) acc[j] = make_float4(0.f, 0.f, 0.f, 0.f);

    const float* base = video + ((size_t)pair * SEQ + (size_t)chunk * ROWS_PER_CHUNK) * VD;

    for (int r = w; r < ROWS_PER_CHUNK; r += 8) {
        const float4* x4 = (const float4*)(base + (size_t)r * VD);
        float4 xv[6];
#pragma unroll
        for (int j = 0; j < 6; j++) xv[j] = x4[lane + 32 * j];
        float s = 0.f;
#pragma unroll
        for (int j = 0; j < 6; j++)
            s += xv[j].x * uv[j].x + xv[j].y * uv[j].y + xv[j].z * uv[j].z + xv[j].w * uv[j].w;
#pragma unroll
        for (int o = 16; o > 0; o >>= 1) s += __shfl_xor_sync(0xffffffffu, s, o);

        if (s > m) {                     // warp-uniform; rare after warmup
            float corr = __expf(m - s);
            l *= corr;
#pragma unroll
            for (int j = 0; j < 6; j++) {
                acc[j].x *= corr; acc[j].y *= corr;
                acc[j].z *= corr; acc[j].w *= corr;
            }
            m = s;
        }
        float p = __expf(s - m);
        l += p;
#pragma unroll
        for (int j = 0; j < 6; j++) {
            acc[j].x += p * xv[j].x; acc[j].y += p * xv[j].y;
            acc[j].z += p * xv[j].z; acc[j].w += p * xv[j].w;
        }
    }

    __shared__ float sm[8], sl[8];
    __shared__ float sacc[8][VD];
    if (lane == 0) { sm[w] = m; sl[w] = l; }
    float4* sa4 = (float4*)sacc[w];
#pragma unroll
    for (int j = 0; j < 6; j++) sa4[lane + 32 * j] = acc[j];
    __syncthreads();

    float M = sm[0];
#pragma unroll
    for (int i = 1; i < 8; i++) M = fmaxf(M, sm[i]);
    float wsc[8], L = 0.f;
#pragma unroll
    for (int i = 0; i < 8; i++) { wsc[i] = __expf(sm[i] - M); L += wsc[i] * sl[i]; }

    for (int d = t; d < VD; d += 256) {
        float a = 0.f;
#pragma unroll
        for (int i = 0; i < 8; i++) a += wsc[i] * sacc[i][d];
        g_Pacc[((size_t)pair * NCHUNK + chunk) * VD + d] = a;
    }
    if (t == 0) { g_Pm[pair * NCHUNK + chunk] = M; g_Pl[pair * NCHUNK + chunk] = L; }
}

// ---------------- combine split-S partials -> r = attn^T @ video ----------------
__global__ __launch_bounds__(256)
void combine_kernel() {
    const int pair = blockIdx.x, t = threadIdx.x;
    __shared__ float wsc[NCHUNK];
    __shared__ float sInvL;
    if (t == 0) {
        float M = g_Pm[pair * NCHUNK];
        for (int c = 1; c < NCHUNK; c++) M = fmaxf(M, g_Pm[pair * NCHUNK + c]);
        float L = 0.f;
        for (int c = 0; c < NCHUNK; c++) {
            float e = __expf(g_Pm[pair * NCHUNK + c] - M);
            wsc[c] = e;
            L += e * g_Pl[pair * NCHUNK + c];
        }
        sInvL = 1.f / L;
    }
    __syncthreads();
    const float invL = sInvL;
    for (int d = t; d < VD; d += 256) {
        float a = 0.f;
#pragma unroll
        for (int c = 0; c < NCHUNK; c++)
            a += wsc[c] * g_Pacc[((size_t)pair * NCHUNK + c) * VD + d];
        g_R[(size_t)pair * VD + d] = a * invL;
    }
}

// ---------------- final: out = softmax(relu(h) @ W2^T + b2 + mask) ----------------
__global__ __launch_bounds__(32)
void final_kernel(const float* __restrict__ W2, const float* __restrict__ b2,
                  const float* __restrict__ omask, float* __restrict__ out) {
    const int pair = blockIdx.x, lane = threadIdx.x;
    float o[NOUT] = {0.f, 0.f, 0.f, 0.f, 0.f};
    for (int h = lane; h < HID; h += 32) {
        float hv = fmaxf(g_H[pair * HID + h], 0.f);
#pragma unroll
        for (int j = 0; j < NOUT; j++) o[j] += hv * W2[j * HID + h];
    }
#pragma unroll
    for (int j = 0; j < NOUT; j++)
#pragma unroll
        for (int off = 16; off > 0; off >>= 1)
            o[j] += __shfl_xor_sync(0xffffffffu, o[j], off);
    if (lane == 0) {
        float x[NOUT], mx = -1e30f;
#pragma unroll
        for (int j = 0; j < NOUT; j++) {
            x[j] = o[j] + b2[j] + omask[pair * NOUT + j];
            mx = fmaxf(mx, x[j]);
        }
        float e[NOUT], s = 0.f;
#pragma unroll
        for (int j = 0; j < NOUT; j++) { e[j] = __expf(x[j] - mx); s += e[j]; }
#pragma unroll
        for (int j = 0; j < NOUT; j++) out[pair * NOUT + j] = e[j] / s;
    }
}

// ---------------- launch ----------------
extern "C" void kernel_launch(void* const* d_in, const int* in_sizes, int n_in,
                              void* d_out, int out_size) {
    (void)in_sizes; (void)n_in; (void)out_size;
    const float* video = (const float*)d_in[0];
    const float* ques  = (const float*)d_in[1];
    const float* omask = (const float*)d_in[3];
    const float* Wvp   = (const float*)d_in[4];
    const float* bvp   = (const float*)d_in[5];
    const float* Wqp   = (const float*)d_in[6];
    const float* bqp   = (const float*)d_in[7];
    const float* Wk    = (const float*)d_in[8];
    const float* Wv    = (const float*)d_in[9];
    const float* Wq    = (const float*)d_in[10];
    const float* W1    = (const float*)d_in[11];
    const float* b1    = (const float*)d_in[12];
    const float* W2    = (const float*)d_in[13];
    const float* b2    = (const float*)d_in[14];
    float* out = (float*)d_out;

    float *X, *QQ, *WKQ, *U, *R, *PH, *H;
    cudaGetSymbolAddress((void**)&X,   g_X);
    cudaGetSymbolAddress((void**)&QQ,  g_QQ);
    cudaGetSymbolAddress((void**)&WKQ, g_WKQ);
    cudaGetSymbolAddress((void**)&U,   g_U);
    cudaGetSymbolAddress((void**)&R,   g_R);
    cudaGetSymbolAddress((void**)&PH,  g_PH);
    cudaGetSymbolAddress((void**)&H,   g_H);

    dim3 blk(128);

    // biases into atomic-accumulated outputs
    init_kernel<<<(PAIRS * HID2 + 255) / 256, 256>>>(bqp, bvp, b1);
    // q = ques[:,:,0,:] @ Wqp^T + bqp -> X[:,512:]   (K=768, R=512, NT)
    gemm_v2<false><<<dim3(4, 5, 6), blk>>>(ques, 32 * VD, Wqp, VD, X + HID, HID2, 128, 1.f);
    // qq = q @ Wq^T                                   (K=512, R=1024, NT)
    gemm_v2<false><<<dim3(8, 5, 4), blk>>>(X + HID, HID2, Wq, HID, QQ, HID2, 128, 1.f);
    // wkq = Wk^T @ qq                                 (K=1024, R=512, TN)
    gemm_v2<true ><<<dim3(4, 5, 8), blk>>>(QQ, HID2, Wk, HID, WKQ, HID, 128, 1.f);
    // u = Wvp^T @ wkq / sqrt(2H)                      (K=512, R=768, TN)
    gemm_v2<true ><<<dim3(6, 5, 4), blk>>>(WKQ, HID, Wvp, VD, U, VD, 128, 1.f / 32.f);
    // flash: single HBM pass over video_enc
    flash_kernel<<<dim3(NCHUNK, PAIRS), 256>>>(video);
    combine_kernel<<<PAIRS, 256>>>();
    // pooled_h = r @ Wvp^T + bvp                       (K=768, R=512, NT)
    gemm_v2<false><<<dim3(4, 5, 6), blk>>>(R, VD, Wvp, VD, PH, HID, 128, 1.f);
    // pooled_v = pooled_h @ Wv^T -> X[:, :512]         (K=512, R=512, NT)
    gemm_v2<false><<<dim3(4, 5, 4), blk>>>(PH, HID, Wv, HID, X, HID2, 128, 1.f);
    // h = X @ W1^T + b1 (relu deferred)                (K=1024, R=512, NT)
    gemm_v2<false><<<dim3(4, 5, 8), blk>>>(X, HID2, W1, HID2, H, HID, 128, 1.f);
    // out = softmax(relu(h) @ W2^T + b2 + output_mask)
    final_kernel<<<PAIRS, 32>>>(W2, b2, omask, out);
}

// round 6
// speedup vs baseline: 1.5959x; 1.2761x over previous
#include <cuda_runtime.h>

#define PAIRS 80
#define SEQ   2048
#define VD    768
#define HID   512
#define HID2  1024
#define NOUT  5
#define NCHUNK 16
#define ROWS_PER_CHUNK (SEQ / NCHUNK)   // 128

// ---------------- scratch (static device globals; no allocs) ----------------
__device__ float g_X[PAIRS * HID2];     // concat: [:,0:512]=pooled_v, [:,512:1024]=q
__device__ float g_QQ[PAIRS * HID2];
__device__ float g_WKQ[PAIRS * HID];
__device__ float g_U[PAIRS * VD];
__device__ float g_R[PAIRS * VD];
__device__ float g_PH[PAIRS * HID];
__device__ float g_H[PAIRS * HID];
__device__ float g_Pacc[PAIRS * NCHUNK * VD];
__device__ float g_Pm[PAIRS * NCHUNK];
__device__ float g_Pl[PAIRS * NCHUNK];

// ---------------- init: bias-initialize split-K atomic outputs ----------------
__global__ void init_kernel(const float* __restrict__ bqp,
                            const float* __restrict__ bvp,
                            const float* __restrict__ b1) {
    int t = blockIdx.x * blockDim.x + threadIdx.x;
    if (t < PAIRS * HID2) {
        int col = t & (HID2 - 1);
        g_X[t]  = (col < HID) ? 0.f : bqp[col - HID];
        g_QQ[t] = 0.f;
    }
    if (t < PAIRS * HID) {
        int col = t & (HID - 1);
        g_WKQ[t] = 0.f;
        g_PH[t]  = bvp[col];
        g_H[t]   = b1[col];
    }
    if (t < PAIRS * VD) g_U[t] = 0.f;
}

// ---------------- skinny GEMM v3: single k-tile, max block count --------------
// out[p][r] += scale * sum_k in[p][k] * W(k,r)
// Block: 128 threads, ONE tile of 16 pairs x 64 r x 32 k. No k-loop.
// grid = (R/64, PAIRS/16, K/32): 640-1280 blocks/stage, ~1 wave, 11+ blocks/SM.
// Per warp per kk: a = LDS.64 (8 distinct 8B chunks, 1 wavefront),
// b = LDS.128 (4 distinct 16B, 1 wavefront), 8 FFMA-instr -> FFMA-issue bound.
// TN: W is [K, R]. NT: W is [R, K] row-major.
template <bool TN>
__global__ __launch_bounds__(128)
void gemm_t(const float* __restrict__ in, int in_ld,
            const float* __restrict__ W, int wld,
            float* __restrict__ out, int out_ld,
            float scale) {
    __shared__ float As[32][18];   // [kk][pair] transposed; 18-pad (8B-aligned a-reads)
    __shared__ float Bs[32][68];   // [kk][r]; 68-pad (16B-aligned b-reads)

    const int tx = threadIdx.x;
    const int r0 = blockIdx.x * 64;
    const int p0 = blockIdx.y * 16;
    const int k0 = blockIdx.z * 32;

    // ---- A: 16p x 32k, one f4 per thread, stored transposed ----
    {
        const int p  = tx >> 3;
        const int kq = tx & 7;
        float4 v = *(const float4*)(in + (size_t)(p0 + p) * in_ld + k0 + 4 * kq);
        As[4 * kq + 0][p] = v.x;
        As[4 * kq + 1][p] = v.y;
        As[4 * kq + 2][p] = v.z;
        As[4 * kq + 3][p] = v.w;
    }
    // ---- B: 32k x 64r, four f4 per thread ----
    if (TN) {
#pragma unroll
        for (int i = 0; i < 4; i++) {
            int idx = tx + 128 * i;
            int kk = idx >> 4, c = idx & 15;
            *(float4*)&Bs[kk][4 * c] =
                *(const float4*)(W + (size_t)(k0 + kk) * wld + r0 + 4 * c);
        }
    } else {
#pragma unroll
        for (int i = 0; i < 4; i++) {
            int idx = tx + 128 * i;
            int r = idx >> 3, kq = idx & 7;
            float4 v = *(const float4*)(W + (size_t)(r0 + r) * wld + k0 + 4 * kq);
            Bs[4 * kq + 0][r] = v.x;
            Bs[4 * kq + 1][r] = v.y;
            Bs[4 * kq + 2][r] = v.z;
            Bs[4 * kq + 3][r] = v.w;
        }
    }
    __syncthreads();

    // ---- compute: warp w covers r in [16w,16w+16); lane: tp=lane>>2 (2 pairs),
    //      rg=lane&3 (4 r). Thread: 2p x 4r = 8 acc. ----
    const int w = tx >> 5;
    const int lane = tx & 31;
    const int tp = lane >> 2;
    const int rcol = 16 * w + 4 * (lane & 3);

    float acc[2][4] = {{0.f, 0.f, 0.f, 0.f}, {0.f, 0.f, 0.f, 0.f}};

#pragma unroll
    for (int kk = 0; kk < 32; kk++) {
        float2 a2 = *(const float2*)&As[kk][2 * tp];
        float4 b4 = *(const float4*)&Bs[kk][rcol];
        acc[0][0] += a2.x * b4.x; acc[0][1] += a2.x * b4.y;
        acc[0][2] += a2.x * b4.z; acc[0][3] += a2.x * b4.w;
        acc[1][0] += a2.y * b4.x; acc[1][1] += a2.y * b4.y;
        acc[1][2] += a2.y * b4.z; acc[1][3] += a2.y * b4.w;
    }

#pragma unroll
    for (int i = 0; i < 2; i++) {
        float* o = out + (size_t)(p0 + 2 * tp + i) * out_ld + r0 + rcol;
#pragma unroll
        for (int j = 0; j < 4; j++)
            atomicAdd(o + j, acc[i][j] * scale);
    }
}

// ---------------- flash: scores + online-softmax pooled accumulation ----------------
// u in registers, NCHUNK=16, 256 threads (8 warps), conditional rescale.
__global__ __launch_bounds__(256)
void flash_kernel(const float* __restrict__ video) {
    const int chunk = blockIdx.x;
    const int pair  = blockIdx.y;
    const int t = threadIdx.x;
    const int w = t >> 5, lane = t & 31;

    const float4* u4 = (const float4*)(g_U + (size_t)pair * VD);
    float4 uv[6];
#pragma unroll
    for (int j = 0; j < 6; j++) uv[j] = u4[lane + 32 * j];

    float m = -1e30f, l = 0.f;
    float4 acc[6];
#pragma unroll
    for (int j = 0; j < 6; j++) acc[j] = make_float4(0.f, 0.f, 0.f, 0.f);

    const float* base = video + ((size_t)pair * SEQ + (size_t)chunk * ROWS_PER_CHUNK) * VD;

    for (int r = w; r < ROWS_PER_CHUNK; r += 8) {
        const float4* x4 = (const float4*)(base + (size_t)r * VD);
        float4 xv[6];
#pragma unroll
        for (int j = 0; j < 6; j++) xv[j] = x4[lane + 32 * j];
        float s = 0.f;
#pragma unroll
        for (int j = 0; j < 6; j++)
            s += xv[j].x * uv[j].x + xv[j].y * uv[j].y + xv[j].z * uv[j].z + xv[j].w * uv[j].w;
#pragma unroll
        for (int o = 16; o > 0; o >>= 1) s += __shfl_xor_sync(0xffffffffu, s, o);

        if (s > m) {                     // warp-uniform; rare after warmup
            float corr = __expf(m - s);
            l *= corr;
#pragma unroll
            for (int j = 0; j < 6; j++) {
                acc[j].x *= corr; acc[j].y *= corr;
                acc[j].z *= corr; acc[j].w *= corr;
            }
            m = s;
        }
        float p = __expf(s - m);
        l += p;
#pragma unroll
        for (int j = 0; j < 6; j++) {
            acc[j].x += p * xv[j].x; acc[j].y += p * xv[j].y;
            acc[j].z += p * xv[j].z; acc[j].w += p * xv[j].w;
        }
    }

    __shared__ float sm[8], sl[8];
    __shared__ float sacc[8][VD];
    if (lane == 0) { sm[w] = m; sl[w] = l; }
    float4* sa4 = (float4*)sacc[w];
#pragma unroll
    for (int j = 0; j < 6; j++) sa4[lane + 32 * j] = acc[j];
    __syncthreads();

    float M = sm[0];
#pragma unroll
    for (int i = 1; i < 8; i++) M = fmaxf(M, sm[i]);
    float wsc[8], L = 0.f;
#pragma unroll
    for (int i = 0; i < 8; i++) { wsc[i] = __expf(sm[i] - M); L += wsc[i] * sl[i]; }

    for (int d = t; d < VD; d += 256) {
        float a = 0.f;
#pragma unroll
        for (int i = 0; i < 8; i++) a += wsc[i] * sacc[i][d];
        g_Pacc[((size_t)pair * NCHUNK + chunk) * VD + d] = a;
    }
    if (t == 0) { g_Pm[pair * NCHUNK + chunk] = M; g_Pl[pair * NCHUNK + chunk] = L; }
}

// ---------------- combine split-S partials -> r = attn^T @ video ----------------
__global__ __launch_bounds__(256)
void combine_kernel() {
    const int pair = blockIdx.x, t = threadIdx.x;
    __shared__ float wsc[NCHUNK];
    __shared__ float sInvL;
    if (t == 0) {
        float M = g_Pm[pair * NCHUNK];
        for (int c = 1; c < NCHUNK; c++) M = fmaxf(M, g_Pm[pair * NCHUNK + c]);
        float L = 0.f;
        for (int c = 0; c < NCHUNK; c++) {
            float e = __expf(g_Pm[pair * NCHUNK + c] - M);
            wsc[c] = e;
            L += e * g_Pl[pair * NCHUNK + c];
        }
        sInvL = 1.f / L;
    }
    __syncthreads();
    const float invL = sInvL;
    for (int d = t; d < VD; d += 256) {
        float a = 0.f;
#pragma unroll
        for (int c = 0; c < NCHUNK; c++)
            a += wsc[c] * g_Pacc[((size_t)pair * NCHUNK + c) * VD + d];
        g_R[(size_t)pair * VD + d] = a * invL;
    }
}

// ---------------- final: out = softmax(relu(h) @ W2^T + b2 + mask) ----------------
__global__ __launch_bounds__(32)
void final_kernel(const float* __restrict__ W2, const float* __restrict__ b2,
                  const float* __restrict__ omask, float* __restrict__ out) {
    const int pair = blockIdx.x, lane = threadIdx.x;
    float o[NOUT] = {0.f, 0.f, 0.f, 0.f, 0.f};
    for (int h = lane; h < HID; h += 32) {
        float hv = fmaxf(g_H[pair * HID + h], 0.f);
#pragma unroll
        for (int j = 0; j < NOUT; j++) o[j] += hv * W2[j * HID + h];
    }
#pragma unroll
    for (int j = 0; j < NOUT; j++)
#pragma unroll
        for (int off = 16; off > 0; off >>= 1)
            o[j] += __shfl_xor_sync(0xffffffffu, o[j], off);
    if (lane == 0) {
        float x[NOUT], mx = -1e30f;
#pragma unroll
        for (int j = 0; j < NOUT; j++) {
            x[j] = o[j] + b2[j] + omask[pair * NOUT + j];
            mx = fmaxf(mx, x[j]);
        }
        float e[NOUT], s = 0.f;
#pragma unroll
        for (int j = 0; j < NOUT; j++) { e[j] = __expf(x[j] - mx); s += e[j]; }
#pragma unroll
        for (int j = 0; j < NOUT; j++) out[pair * NOUT + j] = e[j] / s;
    }
}

// ---------------- launch ----------------
extern "C" void kernel_launch(void* const* d_in, const int* in_sizes, int n_in,
                              void* d_out, int out_size) {
    (void)in_sizes; (void)n_in; (void)out_size;
    const float* video = (const float*)d_in[0];
    const float* ques  = (const float*)d_in[1];
    const float* omask = (const float*)d_in[3];
    const float* Wvp   = (const float*)d_in[4];
    const float* bvp   = (const float*)d_in[5];
    const float* Wqp   = (const float*)d_in[6];
    const float* bqp   = (const float*)d_in[7];
    const float* Wk    = (const float*)d_in[8];
    const float* Wv    = (const float*)d_in[9];
    const float* Wq    = (const float*)d_in[10];
    const float* W1    = (const float*)d_in[11];
    const float* b1    = (const float*)d_in[12];
    const float* W2    = (const float*)d_in[13];
    const float* b2    = (const float*)d_in[14];
    float* out = (float*)d_out;

    float *X, *QQ, *WKQ, *U, *R, *PH, *H;
    cudaGetSymbolAddress((void**)&X,   g_X);
    cudaGetSymbolAddress((void**)&QQ,  g_QQ);
    cudaGetSymbolAddress((void**)&WKQ, g_WKQ);
    cudaGetSymbolAddress((void**)&U,   g_U);
    cudaGetSymbolAddress((void**)&R,   g_R);
    cudaGetSymbolAddress((void**)&PH,  g_PH);
    cudaGetSymbolAddress((void**)&H,   g_H);

    dim3 blk(128);

    // biases into atomic-accumulated outputs
    init_kernel<<<(PAIRS * HID2 + 255) / 256, 256>>>(bqp, bvp, b1);
    // q = ques[:,:,0,:] @ Wqp^T + bqp -> X[:,512:]   (K=768, R=512, NT)
    gemm_t<false><<<dim3(8, 5, 24), blk>>>(ques, 32 * VD, Wqp, VD, X + HID, HID2, 1.f);
    // qq = q @ Wq^T                                   (K=512, R=1024, NT)
    gemm_t<false><<<dim3(16, 5, 16), blk>>>(X + HID, HID2, Wq, HID, QQ, HID2, 1.f);
    // wkq = Wk^T @ qq                                 (K=1024, R=512, TN)
    gemm_t<true ><<<dim3(8, 5, 32), blk>>>(QQ, HID2, Wk, HID, WKQ, HID, 1.f);
    // u = Wvp^T @ wkq / sqrt(2H)                      (K=512, R=768, TN)
    gemm_t<true ><<<dim3(12, 5, 16), blk>>>(WKQ, HID, Wvp, VD, U, VD, 1.f / 32.f);
    // flash: single HBM pass over video_enc
    flash_kernel<<<dim3(NCHUNK, PAIRS), 256>>>(video);
    combine_kernel<<<PAIRS, 256>>>();
    // pooled_h = r @ Wvp^T + bvp                       (K=768, R=512, NT)
    gemm_t<false><<<dim3(8, 5, 24), blk>>>(R, VD, Wvp, VD, PH, HID, 1.f);
    // pooled_v = pooled_h @ Wv^T -> X[:, :512]         (K=512, R=512, NT)
    gemm_t<false><<<dim3(8, 5, 16), blk>>>(PH, HID, Wv, HID, X, HID2, 1.f);
    // h = X @ W1^T + b1 (relu deferred)                (K=1024, R=512, NT)
    gemm_t<false><<<dim3(8, 5, 32), blk>>>(X, HID2, W1, HID2, H, HID, 1.f);
    // out = softmax(relu(h) @ W2^T + b2 + output_mask)
    final_kernel<<<PAIRS, 32>>>(W2, b2, omask, out);
}